// round 8
// baseline (speedup 1.0000x reference)
#include <cuda_runtime.h>

// Problem constants (fixed by the dataset: B=16, H=W=512, K=1024)
#define NB    16
#define HH    512
#define WW    512
#define KK    1024
#define NROWS (NB * KK)        // 16384 segments / tokens
#define NPIX  (HH * WW)        // 262144 pixels per image
#define NQUAD (NB * NPIX / 4)  // 1048576 float4/int4 quads
#define BN_EPS 1e-5f

// Scratch (device globals — no runtime allocation allowed)
__device__ float4 g_acc[NROWS];          // per-segment sums: fx, fy, xx, yy
__device__ float  g_cnt[NROWS];          // per-segment counts
__device__ float  g_s1[128];             // BN1 stats: sum[64], sumsq[64]
__device__ float  g_s2[64];              // BN2 stats: sum[32], sumsq[32]

// ---------------------------------------------------------------------------
// K0: zero the accumulators (graph replays: must rebuild every launch)
// ---------------------------------------------------------------------------
__global__ void k_zero() {
    int i = blockIdx.x * blockDim.x + threadIdx.x;   // 64*256 = 16384 threads
    g_acc[i] = make_float4(0.f, 0.f, 0.f, 0.f);
    g_cnt[i] = 0.f;
    if (i < 128) g_s1[i] = 0.f;
    if (i < 64)  g_s2[i] = 0.f;
}

// ---------------------------------------------------------------------------
// K1: pooling via global vector REDs. One thread = 4 consecutive pixels.
// Per pixel: 1x RED.128 (fx,fy,xx,yy) + 1x RED.32 (count).
// ---------------------------------------------------------------------------
__global__ void k_pool(const int4* __restrict__ lab,
                       const float4* __restrict__ fx4,
                       const float4* __restrict__ fy4) {
    int q = blockIdx.x * blockDim.x + threadIdx.x;
    if (q >= NQUAD) return;

    int4   l = lab[q];
    float4 a = fx4[q];
    float4 b = fy4[q];

    int pix0 = q << 2;
    int img  = pix0 >> 18;              // / NPIX
    int p    = pix0 & (NPIX - 1);
    int i    = p >> 9;                  // row   (dim 2 -> xx)
    int j    = p & (WW - 1);            // col   (dim 3 -> yy)

    const float st = 2.0f / 511.0f;
    float xx = (float)i * st - 1.0f;
    float y0 = (float)j * st - 1.0f;
    int base = img << 10;

    int s0 = base + l.x, s1 = base + l.y, s2 = base + l.z, s3 = base + l.w;
    atomicAdd(&g_acc[s0], make_float4(a.x, b.x, xx, y0));
    atomicAdd(&g_acc[s1], make_float4(a.y, b.y, xx, y0 + st));
    atomicAdd(&g_acc[s2], make_float4(a.z, b.z, xx, y0 + 2.f * st));
    atomicAdd(&g_acc[s3], make_float4(a.w, b.w, xx, y0 + 3.f * st));
    atomicAdd(&g_cnt[s0], 1.0f);
    atomicAdd(&g_cnt[s1], 1.0f);
    atomicAdd(&g_cnt[s2], 1.0f);
    atomicAdd(&g_cnt[s3], 1.0f);
}

// ---------------------------------------------------------------------------
// Helper: per-row 5-vector input (t, mean fx, mean fy, mean xx, mean yy)
// ---------------------------------------------------------------------------
__device__ __forceinline__ void row_input(int r, const int* frame_idx,
                                          const int* n_frames,
                                          float& x0, float& x1, float& x2,
                                          float& x3, float& x4) {
    float4 a = g_acc[r];
    float  c = fmaxf(g_cnt[r], 1.0f);
    float  inv = 1.0f / c;
    x0 = (float)frame_idx[r >> 10] / (float)(n_frames[0] - 1);
    x1 = a.x * inv; x2 = a.y * inv; x3 = a.z * inv; x4 = a.w * inv;
}

// ---------------------------------------------------------------------------
// K2: BN1 statistics. Recompute y = conv(x) per row, reduce sum/sumsq per
// feature via warp butterfly + shared cross-warp + 128 global REDs / block.
// ---------------------------------------------------------------------------
__global__ void k_statsA(const float* __restrict__ conv_w,   // [64,5]
                         const float* __restrict__ conv_b,   // [64]
                         const int*   __restrict__ frame_idx,
                         const int*   __restrict__ n_frames) {
    __shared__ float w[320], bb[64];
    __shared__ float psum[8][64], psq[8][64];
    int tid = threadIdx.x;                  // 256
    for (int i = tid; i < 320; i += 256) w[i] = conv_w[i];
    if (tid < 64) bb[tid] = conv_b[tid];
    __syncthreads();

    int r = blockIdx.x * 256 + tid;         // 64 blocks
    float x0, x1, x2, x3, x4;
    row_input(r, frame_idx, n_frames, x0, x1, x2, x3, x4);

    int wid = tid >> 5, lane = tid & 31;
    #pragma unroll 8
    for (int f = 0; f < 64; f++) {
        float y = bb[f] + w[f*5]*x0 + w[f*5+1]*x1 + w[f*5+2]*x2
                        + w[f*5+3]*x3 + w[f*5+4]*x4;
        float s = y, q = y * y;
        #pragma unroll
        for (int o = 16; o > 0; o >>= 1) {
            s += __shfl_xor_sync(0xffffffffu, s, o);
            q += __shfl_xor_sync(0xffffffffu, q, o);
        }
        if (lane == 0) { psum[wid][f] = s; psq[wid][f] = q; }
    }
    __syncthreads();
    if (tid < 64) {
        float s = 0.f;
        #pragma unroll
        for (int k = 0; k < 8; k++) s += psum[k][tid];
        atomicAdd(&g_s1[tid], s);
    } else if (tid < 128) {
        int f = tid - 64;
        float q = 0.f;
        #pragma unroll
        for (int k = 0; k < 8; k++) q += psq[k][f];
        atomicAdd(&g_s1[64 + f], q);
    }
}

// ---------------------------------------------------------------------------
// K3: BN2 statistics. Recompute y -> BN1 -> ReLU -> z = lin(h), reduce
// sum/sumsq of z per output feature.
// ---------------------------------------------------------------------------
__global__ void k_statsB(const float* __restrict__ conv_w,
                         const float* __restrict__ conv_b,
                         const int*   __restrict__ frame_idx,
                         const int*   __restrict__ n_frames,
                         const float* __restrict__ bn1_g,
                         const float* __restrict__ bn1_b,
                         const float* __restrict__ lin_w,   // [32,64]
                         const float* __restrict__ lin_b) { // [32]
    __shared__ float w[320], bb[64], sc[64], sh[64], lbb[32];
    __shared__ float4 lw4[512];             // [32][16]
    __shared__ float psum[4][32], psq[4][32];
    int tid = threadIdx.x;                  // 128
    for (int i = tid; i < 320; i += 128) w[i] = conv_w[i];
    for (int i = tid; i < 512; i += 128) lw4[i] = ((const float4*)lin_w)[i];
    if (tid < 64) {
        bb[tid] = conv_b[tid];
        float mean = g_s1[tid] * (1.0f / NROWS);
        float var  = g_s1[64 + tid] * (1.0f / NROWS) - mean * mean;
        float s = bn1_g[tid] * rsqrtf(var + BN_EPS);
        sc[tid] = s;
        sh[tid] = bn1_b[tid] - mean * s;
    }
    if (tid < 32) lbb[tid] = lin_b[tid];
    __syncthreads();

    int r = blockIdx.x * 128 + tid;         // 128 blocks
    float x0, x1, x2, x3, x4;
    row_input(r, frame_idx, n_frames, x0, x1, x2, x3, x4);

    float z[32];
    #pragma unroll
    for (int o = 0; o < 32; o++) z[o] = lbb[o];

    #pragma unroll 4
    for (int fq = 0; fq < 16; fq++) {
        int f = fq * 4;
        float h[4];
        #pragma unroll
        for (int k = 0; k < 4; k++) {
            int ff = f + k;
            float y = bb[ff] + w[ff*5]*x0 + w[ff*5+1]*x1 + w[ff*5+2]*x2
                             + w[ff*5+3]*x3 + w[ff*5+4]*x4;
            h[k] = fmaxf(y * sc[ff] + sh[ff], 0.f);
        }
        #pragma unroll
        for (int o = 0; o < 32; o++) {
            float4 wv = lw4[o * 16 + fq];
            z[o] += h[0]*wv.x + h[1]*wv.y + h[2]*wv.z + h[3]*wv.w;
        }
    }

    int wid = tid >> 5, lane = tid & 31;
    #pragma unroll
    for (int o = 0; o < 32; o++) {
        float s = z[o], q = z[o] * z[o];
        #pragma unroll
        for (int off = 16; off > 0; off >>= 1) {
            s += __shfl_xor_sync(0xffffffffu, s, off);
            q += __shfl_xor_sync(0xffffffffu, q, off);
        }
        if (lane == 0) { psum[wid][o] = s; psq[wid][o] = q; }
    }
    __syncthreads();
    if (tid < 32) {
        atomicAdd(&g_s2[tid], psum[0][tid] + psum[1][tid] + psum[2][tid] + psum[3][tid]);
    } else if (tid < 64) {
        int o = tid - 32;
        atomicAdd(&g_s2[32 + o], psq[0][o] + psq[1][o] + psq[2][o] + psq[3][o]);
    }
}

// ---------------------------------------------------------------------------
// K4: final. Recompute y -> BN1 -> ReLU -> z -> BN2 -> ReLU -> L2-normalize,
// write row-major [16384, 32].
// ---------------------------------------------------------------------------
__global__ void k_out(const float* __restrict__ conv_w,
                      const float* __restrict__ conv_b,
                      const int*   __restrict__ frame_idx,
                      const int*   __restrict__ n_frames,
                      const float* __restrict__ bn1_g,
                      const float* __restrict__ bn1_b,
                      const float* __restrict__ lin_w,
                      const float* __restrict__ lin_b,
                      const float* __restrict__ bn2_g,
                      const float* __restrict__ bn2_b,
                      float* __restrict__ out) {
    __shared__ float w[320], bb[64], sc[64], sh[64], lbb[32], sc2[32], sh2[32];
    __shared__ float4 lw4[512];
    int tid = threadIdx.x;                  // 128
    for (int i = tid; i < 320; i += 128) w[i] = conv_w[i];
    for (int i = tid; i < 512; i += 128) lw4[i] = ((const float4*)lin_w)[i];
    if (tid < 64) {
        bb[tid] = conv_b[tid];
        float mean = g_s1[tid] * (1.0f / NROWS);
        float var  = g_s1[64 + tid] * (1.0f / NROWS) - mean * mean;
        float s = bn1_g[tid] * rsqrtf(var + BN_EPS);
        sc[tid] = s;
        sh[tid] = bn1_b[tid] - mean * s;
    }
    if (tid < 32) {
        lbb[tid] = lin_b[tid];
        float mean = g_s2[tid] * (1.0f / NROWS);
        float var  = g_s2[32 + tid] * (1.0f / NROWS) - mean * mean;
        float s = bn2_g[tid] * rsqrtf(var + BN_EPS);
        sc2[tid] = s;
        sh2[tid] = bn2_b[tid] - mean * s;
    }
    __syncthreads();

    int r = blockIdx.x * 128 + tid;         // 128 blocks
    float x0, x1, x2, x3, x4;
    row_input(r, frame_idx, n_frames, x0, x1, x2, x3, x4);

    float z[32];
    #pragma unroll
    for (int o = 0; o < 32; o++) z[o] = lbb[o];

    #pragma unroll 4
    for (int fq = 0; fq < 16; fq++) {
        int f = fq * 4;
        float h[4];
        #pragma unroll
        for (int k = 0; k < 4; k++) {
            int ff = f + k;
            float y = bb[ff] + w[ff*5]*x0 + w[ff*5+1]*x1 + w[ff*5+2]*x2
                             + w[ff*5+3]*x3 + w[ff*5+4]*x4;
            h[k] = fmaxf(y * sc[ff] + sh[ff], 0.f);
        }
        #pragma unroll
        for (int o = 0; o < 32; o++) {
            float4 wv = lw4[o * 16 + fq];
            z[o] += h[0]*wv.x + h[1]*wv.y + h[2]*wv.z + h[3]*wv.w;
        }
    }

    float ss = 0.f;
    #pragma unroll
    for (int o = 0; o < 32; o++) {
        float t = fmaxf(z[o] * sc2[o] + sh2[o], 0.f);
        z[o] = t;
        ss += t * t;
    }
    float inv = 1.0f / fmaxf(sqrtf(ss), 1e-8f);
    float4* op = (float4*)(out + (size_t)r * 32);
    #pragma unroll
    for (int q = 0; q < 8; q++)
        op[q] = make_float4(z[4*q]*inv, z[4*q+1]*inv, z[4*q+2]*inv, z[4*q+3]*inv);
}

// ---------------------------------------------------------------------------
extern "C" void kernel_launch(void* const* d_in, const int* in_sizes, int n_in,
                              void* d_out, int out_size) {
    const int*   labels  = (const int*)  d_in[0];
    const float* fx      = (const float*)d_in[1];
    const float* fy      = (const float*)d_in[2];
    const int*   fidx    = (const int*)  d_in[3];
    const int*   nfrm    = (const int*)  d_in[4];
    // d_in[5] = n_labels (compile-time 1024)
    const float* conv_w  = (const float*)d_in[6];
    const float* conv_b  = (const float*)d_in[7];
    const float* bn1_g   = (const float*)d_in[8];
    const float* bn1_b   = (const float*)d_in[9];
    const float* lin_w   = (const float*)d_in[10];
    const float* lin_b   = (const float*)d_in[11];
    const float* bn2_g   = (const float*)d_in[12];
    const float* bn2_b   = (const float*)d_in[13];

    k_zero<<<64, 256>>>();
    k_pool<<<NQUAD / 256, 256>>>((const int4*)labels,
                                 (const float4*)fx, (const float4*)fy);
    k_statsA<<<64, 256>>>(conv_w, conv_b, fidx, nfrm);
    k_statsB<<<128, 128>>>(conv_w, conv_b, fidx, nfrm, bn1_g, bn1_b, lin_w, lin_b);
    k_out<<<128, 128>>>(conv_w, conv_b, fidx, nfrm, bn1_g, bn1_b,
                        lin_w, lin_b, bn2_g, bn2_b, (float*)d_out);
}

// round 9
// speedup vs baseline: 1.9261x; 1.9261x over previous
#include <cuda_runtime.h>

// Problem constants (fixed by the dataset: B=16, H=W=512, K=1024)
#define NB    16
#define HH    512
#define WW    512
#define KK    1024
#define NROWS (NB * KK)        // 16384 segments / tokens
#define NPIX  (HH * WW)        // 262144 pixels per image
#define QPI   (NPIX / 4)       // 65536 quads per image
#define NREP  8
#define BN_EPS 1e-5f

typedef unsigned long long u64;

// Scratch (device globals — no runtime allocation allowed)
__device__ float2 g_fxy[NREP][NROWS];   // replicated per-segment (sum fx, sum fy)
__device__ u64    g_ij [NREP][NROWS];   // replicated packed (cnt<<48 | sum_i<<24 | sum_j)
__device__ float4 g_x[NROWS];           // per-row pooled means (fx, fy, xx, yy)
__device__ double g_mom[20];            // Σ over rows of x (5) + upper-tri x x^T (15)
__device__ float  g_s2[64];             // BN2 stats: sum[32], sumsq[32]

// ---------------------------------------------------------------------------
// K0: zero replicated accumulators + moment buffers
// ---------------------------------------------------------------------------
__global__ void k_zero() {
    int i = blockIdx.x * blockDim.x + threadIdx.x;   // 256*512 = 131072 = NREP*NROWS
    ((float2*)g_fxy)[i] = make_float2(0.f, 0.f);
    ((u64*)g_ij)[i] = 0ULL;
    if (i < 20) g_mom[i] = 0.0;
    if (i < 64) g_s2[i] = 0.f;
}

// ---------------------------------------------------------------------------
// K1: pooling. Blocks interleave images (bid&15) so resident blocks span all
// 16 images' address ranges; 8-way replica (by within-image block) cuts
// per-address contention. Per pixel: RED.64 float2 + RED.64 packed-int.
// ---------------------------------------------------------------------------
__global__ void k_pool(const int4* __restrict__ lab,
                       const float4* __restrict__ fx4,
                       const float4* __restrict__ fy4) {
    int tid = threadIdx.x;
    int bid = blockIdx.x;               // 4096 blocks
    int img = bid & 15;
    int blk = bid >> 4;                 // 0..255 within image
    int rep = blk & (NREP - 1);
    int qi  = blk * 256 + tid;          // quad index within image
    int q   = img * QPI + qi;           // global quad

    int4   l = lab[q];
    float4 a = fx4[q];
    float4 b = fy4[q];

    int p0 = qi << 2;                   // pixel within image
    int i  = p0 >> 9;                   // dim-2 index (xx)
    int j  = p0 & (WW - 1);             // dim-3 index (yy), j..j+3

    int base = img << 10;
    u64 c0 = (1ULL << 48) | ((u64)i << 24);

    int s0 = base + l.x, s1 = base + l.y, s2 = base + l.z, s3 = base + l.w;
    atomicAdd(&g_fxy[rep][s0], make_float2(a.x, b.x));
    atomicAdd(&g_fxy[rep][s1], make_float2(a.y, b.y));
    atomicAdd(&g_fxy[rep][s2], make_float2(a.z, b.z));
    atomicAdd(&g_fxy[rep][s3], make_float2(a.w, b.w));
    atomicAdd(&g_ij[rep][s0], c0 + (u64)(unsigned)j);
    atomicAdd(&g_ij[rep][s1], c0 + (u64)(unsigned)(j + 1));
    atomicAdd(&g_ij[rep][s2], c0 + (u64)(unsigned)(j + 2));
    atomicAdd(&g_ij[rep][s3], c0 + (u64)(unsigned)(j + 3));
}

// ---------------------------------------------------------------------------
// K2: fold replicas -> per-row means g_x, and reduce the 20 input moments
// (Σx and Σ x x^T including the t channel) into g_mom (double).
// ---------------------------------------------------------------------------
__global__ void k_mom(const int* __restrict__ frame_idx,
                      const int* __restrict__ n_frames) {
    __shared__ float part[8][20];
    int tid = threadIdx.x;                  // 256
    int r = blockIdx.x * 256 + tid;         // 64 blocks

    float2 f = make_float2(0.f, 0.f);
    u64 pk = 0ULL;
    #pragma unroll
    for (int k = 0; k < NREP; k++) {
        float2 t = g_fxy[k][r];
        f.x += t.x; f.y += t.y;
        pk += g_ij[k][r];
    }
    float cnt = (float)(unsigned)(pk >> 48);
    float si  = (float)(unsigned)((pk >> 24) & 0xFFFFFFu);
    float sj  = (float)(unsigned)(pk & 0xFFFFFFu);

    const float st = 2.0f / 511.0f;
    float inv = 1.0f / fmaxf(cnt, 1.0f);
    float x1 = f.x * inv;
    float x2 = f.y * inv;
    float x3 = (st * si - cnt) * inv;       // Σxx = st*Σi − cnt
    float x4 = (st * sj - cnt) * inv;
    g_x[r] = make_float4(x1, x2, x3, x4);

    float x0 = (float)frame_idx[r >> 10] / (float)(n_frames[0] - 1);

    float v[5] = {x0, x1, x2, x3, x4};
    float m[20];
    #pragma unroll
    for (int p = 0; p < 5; p++) m[p] = v[p];
    int k = 5;
    #pragma unroll
    for (int p = 0; p < 5; p++)
        #pragma unroll
        for (int q2 = p; q2 < 5; q2++) m[k++] = v[p] * v[q2];

    #pragma unroll
    for (int t = 0; t < 20; t++)
        #pragma unroll
        for (int o = 16; o > 0; o >>= 1)
            m[t] += __shfl_xor_sync(0xffffffffu, m[t], o);

    int wid = tid >> 5, lane = tid & 31;
    if (lane == 0)
        #pragma unroll
        for (int t = 0; t < 20; t++) part[wid][t] = m[t];
    __syncthreads();
    if (tid < 20) {
        double s = 0.0;
        #pragma unroll
        for (int w = 0; w < 8; w++) s += (double)part[w][tid];
        atomicAdd(&g_mom[tid], s);
    }
}

// ---------------------------------------------------------------------------
// Shared setup: analytic BN1 scale/shift from input moments.
// mean_f = w_f·E[x] + b_f ;  E[y^2]_f = w_f^T E[xx^T] w_f + 2 b_f w_f·E[x] + b_f^2
// ---------------------------------------------------------------------------
__device__ __forceinline__ void bn1_setup(int tid,
                                          const float* conv_w, const float* conv_b,
                                          const float* bn1_g, const float* bn1_b,
                                          float* sc, float* sh) {
    if (tid < 64) {
        const double invN = 1.0 / (double)NROWS;
        double mp[5];
        #pragma unroll
        for (int p = 0; p < 5; p++) mp[p] = g_mom[p] * invN;
        double Mf[5][5];
        int k = 5;
        #pragma unroll
        for (int p = 0; p < 5; p++)
            #pragma unroll
            for (int q2 = p; q2 < 5; q2++) {
                double val = g_mom[k++] * invN;
                Mf[p][q2] = val; Mf[q2][p] = val;
            }
        double wv[5];
        #pragma unroll
        for (int p = 0; p < 5; p++) wv[p] = (double)conv_w[tid * 5 + p];
        double b = (double)conv_b[tid];
        double dot = 0.0, quad = 0.0;
        #pragma unroll
        for (int p = 0; p < 5; p++) {
            dot += wv[p] * mp[p];
            double row = 0.0;
            #pragma unroll
            for (int q2 = 0; q2 < 5; q2++) row += wv[q2] * Mf[p][q2];
            quad += wv[p] * row;
        }
        double mean = dot + b;
        double ey2  = quad + 2.0 * b * dot + b * b;
        double var  = ey2 - mean * mean;
        double s = (double)bn1_g[tid] / sqrt(var + (double)BN_EPS);
        sc[tid] = (float)s;
        sh[tid] = (float)((double)bn1_b[tid] - mean * s);
    }
}

// ---------------------------------------------------------------------------
// Helper: per-row hidden + z computation (shared by statsB and out)
// ---------------------------------------------------------------------------
__device__ __forceinline__ void compute_z(int r, float x0,
                                          const float* w, const float* bb,
                                          const float* sc, const float* sh,
                                          const float4* lw4, const float* lbb,
                                          float* z) {
    float4 xv = g_x[r];
    float x1 = xv.x, x2 = xv.y, x3 = xv.z, x4 = xv.w;

    #pragma unroll
    for (int o = 0; o < 32; o++) z[o] = lbb[o];

    #pragma unroll 4
    for (int fq = 0; fq < 16; fq++) {
        int f = fq * 4;
        float h[4];
        #pragma unroll
        for (int kk = 0; kk < 4; kk++) {
            int ff = f + kk;
            float y = bb[ff] + w[ff*5]*x0 + w[ff*5+1]*x1 + w[ff*5+2]*x2
                             + w[ff*5+3]*x3 + w[ff*5+4]*x4;
            h[kk] = fmaxf(y * sc[ff] + sh[ff], 0.f);
        }
        #pragma unroll
        for (int o = 0; o < 32; o++) {
            float4 wv = lw4[o * 16 + fq];
            z[o] += h[0]*wv.x + h[1]*wv.y + h[2]*wv.z + h[3]*wv.w;
        }
    }
}

// ---------------------------------------------------------------------------
// K3: BN2 statistics (z sum/sumsq per output feature)
// ---------------------------------------------------------------------------
__global__ void k_statsB(const float* __restrict__ conv_w,
                         const float* __restrict__ conv_b,
                         const int*   __restrict__ frame_idx,
                         const int*   __restrict__ n_frames,
                         const float* __restrict__ bn1_g,
                         const float* __restrict__ bn1_b,
                         const float* __restrict__ lin_w,   // [32,64]
                         const float* __restrict__ lin_b) { // [32]
    __shared__ float w[320], bb[64], sc[64], sh[64], lbb[32];
    __shared__ float4 lw4[512];
    __shared__ float psum[4][32], psq[4][32];
    int tid = threadIdx.x;                  // 128
    for (int i = tid; i < 320; i += 128) w[i] = conv_w[i];
    for (int i = tid; i < 512; i += 128) lw4[i] = ((const float4*)lin_w)[i];
    if (tid < 64) bb[tid] = conv_b[tid];
    if (tid < 32) lbb[tid] = lin_b[tid];
    bn1_setup(tid, conv_w, conv_b, bn1_g, bn1_b, sc, sh);
    __syncthreads();

    int r = blockIdx.x * 128 + tid;         // 128 blocks
    float x0 = (float)frame_idx[r >> 10] / (float)(n_frames[0] - 1);
    float z[32];
    compute_z(r, x0, w, bb, sc, sh, lw4, lbb, z);

    int wid = tid >> 5, lane = tid & 31;
    #pragma unroll
    for (int o = 0; o < 32; o++) {
        float s = z[o], q = z[o] * z[o];
        #pragma unroll
        for (int off = 16; off > 0; off >>= 1) {
            s += __shfl_xor_sync(0xffffffffu, s, off);
            q += __shfl_xor_sync(0xffffffffu, q, off);
        }
        if (lane == 0) { psum[wid][o] = s; psq[wid][o] = q; }
    }
    __syncthreads();
    if (tid < 32) {
        atomicAdd(&g_s2[tid], psum[0][tid] + psum[1][tid] + psum[2][tid] + psum[3][tid]);
    } else if (tid < 64) {
        int o = tid - 32;
        atomicAdd(&g_s2[32 + o], psq[0][o] + psq[1][o] + psq[2][o] + psq[3][o]);
    }
}

// ---------------------------------------------------------------------------
// K4: final. BN2 + ReLU + L2-normalize, write row-major [16384, 32].
// ---------------------------------------------------------------------------
__global__ void k_out(const float* __restrict__ conv_w,
                      const float* __restrict__ conv_b,
                      const int*   __restrict__ frame_idx,
                      const int*   __restrict__ n_frames,
                      const float* __restrict__ bn1_g,
                      const float* __restrict__ bn1_b,
                      const float* __restrict__ lin_w,
                      const float* __restrict__ lin_b,
                      const float* __restrict__ bn2_g,
                      const float* __restrict__ bn2_b,
                      float* __restrict__ out) {
    __shared__ float w[320], bb[64], sc[64], sh[64], lbb[32], sc2[32], sh2[32];
    __shared__ float4 lw4[512];
    int tid = threadIdx.x;                  // 128
    for (int i = tid; i < 320; i += 128) w[i] = conv_w[i];
    for (int i = tid; i < 512; i += 128) lw4[i] = ((const float4*)lin_w)[i];
    if (tid < 64) bb[tid] = conv_b[tid];
    bn1_setup(tid, conv_w, conv_b, bn1_g, bn1_b, sc, sh);
    if (tid < 32) {
        lbb[tid] = lin_b[tid];
        float mean = g_s2[tid] * (1.0f / NROWS);
        float var  = g_s2[32 + tid] * (1.0f / NROWS) - mean * mean;
        float s = bn2_g[tid] * rsqrtf(var + BN_EPS);
        sc2[tid] = s;
        sh2[tid] = bn2_b[tid] - mean * s;
    }
    __syncthreads();

    int r = blockIdx.x * 128 + tid;         // 128 blocks
    float x0 = (float)frame_idx[r >> 10] / (float)(n_frames[0] - 1);
    float z[32];
    compute_z(r, x0, w, bb, sc, sh, lw4, lbb, z);

    float ss = 0.f;
    #pragma unroll
    for (int o = 0; o < 32; o++) {
        float t = fmaxf(z[o] * sc2[o] + sh2[o], 0.f);
        z[o] = t;
        ss += t * t;
    }
    float inv = 1.0f / fmaxf(sqrtf(ss), 1e-8f);
    float4* op = (float4*)(out + (size_t)r * 32);
    #pragma unroll
    for (int q = 0; q < 8; q++)
        op[q] = make_float4(z[4*q]*inv, z[4*q+1]*inv, z[4*q+2]*inv, z[4*q+3]*inv);
}

// ---------------------------------------------------------------------------
extern "C" void kernel_launch(void* const* d_in, const int* in_sizes, int n_in,
                              void* d_out, int out_size) {
    const int*   labels  = (const int*)  d_in[0];
    const float* fx      = (const float*)d_in[1];
    const float* fy      = (const float*)d_in[2];
    const int*   fidx    = (const int*)  d_in[3];
    const int*   nfrm    = (const int*)  d_in[4];
    // d_in[5] = n_labels (compile-time 1024)
    const float* conv_w  = (const float*)d_in[6];
    const float* conv_b  = (const float*)d_in[7];
    const float* bn1_g   = (const float*)d_in[8];
    const float* bn1_b   = (const float*)d_in[9];
    const float* lin_w   = (const float*)d_in[10];
    const float* lin_b   = (const float*)d_in[11];
    const float* bn2_g   = (const float*)d_in[12];
    const float* bn2_b   = (const float*)d_in[13];

    k_zero<<<256, 512>>>();
    k_pool<<<4096, 256>>>((const int4*)labels,
                          (const float4*)fx, (const float4*)fy);
    k_mom<<<64, 256>>>(fidx, nfrm);
    k_statsB<<<128, 128>>>(conv_w, conv_b, fidx, nfrm, bn1_g, bn1_b, lin_w, lin_b);
    k_out<<<128, 128>>>(conv_w, conv_b, fidx, nfrm, bn1_g, bn1_b,
                        lin_w, lin_b, bn2_g, bn2_b, (float*)d_out);
}